// round 1
// baseline (speedup 1.0000x reference)
#include <cuda_runtime.h>
#include <math.h>

#define SQ   2048
#define EM   768
#define NH   12
#define DH   64
#define FFD  3072
#define NL   4
#define EPSF 1e-5f
#define NCHUNK 8

// ---------------- scratch (no allocations allowed) ----------------
__device__ float g_x[SQ*EM];     // residual stream
__device__ float g_h[SQ*EM];     // layernorm output
__device__ float g_q[SQ*EM];
__device__ float g_k[SQ*EM];
__device__ float g_v[SQ*EM];
__device__ float g_ao[SQ*EM];    // attention output (pre o-proj)
__device__ float g_ff[SQ*FFD];   // MLP hidden
__device__ float g_Mp[NH*NCHUNK*DH*DH]; // partial K^T V per head per chunk

// ---------------- x = emb + wpe ----------------
__global__ void add_wpe_k(const float* __restrict__ emb, const float* __restrict__ wpe) {
    int i = blockIdx.x * blockDim.x + threadIdx.x;
    if (i < SQ*EM) g_x[i] = emb[i] + wpe[i];
}

// ---------------- layernorm: one block per row ----------------
__global__ void layernorm_k(const float* __restrict__ in, float* __restrict__ out,
                            const float* __restrict__ g, const float* __restrict__ b) {
    int row = blockIdx.x;
    const float* x = in + row * EM;
    float s = 0.f, s2 = 0.f;
    for (int j = threadIdx.x; j < EM; j += 256) {
        float v = x[j];
        s += v; s2 += v * v;
    }
    __shared__ float rs[32], rs2[32];
    #pragma unroll
    for (int o = 16; o; o >>= 1) {
        s  += __shfl_down_sync(0xffffffffu, s,  o);
        s2 += __shfl_down_sync(0xffffffffu, s2, o);
    }
    int w = threadIdx.x >> 5, l = threadIdx.x & 31;
    if (l == 0) { rs[w] = s; rs2[w] = s2; }
    __syncthreads();
    if (w == 0) {
        s  = (l < 8) ? rs[l]  : 0.f;
        s2 = (l < 8) ? rs2[l] : 0.f;
        #pragma unroll
        for (int o = 4; o; o >>= 1) {
            s  += __shfl_down_sync(0xffffffffu, s,  o);
            s2 += __shfl_down_sync(0xffffffffu, s2, o);
        }
        if (l == 0) { rs[0] = s; rs2[0] = s2; }
    }
    __syncthreads();
    float mu  = rs[0] * (1.0f / EM);
    float var = rs2[0] * (1.0f / EM) - mu * mu;
    float inv = rsqrtf(var + EPSF);
    for (int j = threadIdx.x; j < EM; j += 256)
        out[row * EM + j] = (x[j] - mu) * inv * g[j] + b[j];
}

// ---------------- tiled GEMM: C = epi(A[MxK] @ W[KxN] + bias [, +res]) ----------------
// BM=BN=64, BK=16, 256 threads, 4x4 per thread. All dims divisible.
template<bool GELU, bool RES>
__global__ void __launch_bounds__(256)
gemm64_k(const float* __restrict__ A, const float* __restrict__ W,
         const float* __restrict__ bias, const float* __restrict__ res,
         float* __restrict__ C, int M, int N, int K) {
    __shared__ float As[16][65];
    __shared__ float Bs[16][65];
    const int row0 = blockIdx.y * 64, col0 = blockIdx.x * 64;
    const int tid = threadIdx.x;
    const int tx = tid & 15, ty = tid >> 4;
    float acc[4][4] = {};
    for (int k0 = 0; k0 < K; k0 += 16) {
        #pragma unroll
        for (int i = 0; i < 4; i++) {
            int idx = tid + i * 256;
            int m  = idx >> 4, kk = idx & 15;
            As[kk][m] = A[(row0 + m) * K + k0 + kk];
            int n  = idx & 63, kk2 = idx >> 6;
            Bs[kk2][n] = W[(k0 + kk2) * N + col0 + n];
        }
        __syncthreads();
        #pragma unroll
        for (int kk = 0; kk < 16; kk++) {
            float a[4], bb[4];
            #pragma unroll
            for (int i = 0; i < 4; i++) a[i]  = As[kk][ty + i * 16];
            #pragma unroll
            for (int j = 0; j < 4; j++) bb[j] = Bs[kk][tx + j * 16];
            #pragma unroll
            for (int i = 0; i < 4; i++)
                #pragma unroll
                for (int j = 0; j < 4; j++)
                    acc[i][j] += a[i] * bb[j];
        }
        __syncthreads();
    }
    #pragma unroll
    for (int i = 0; i < 4; i++) {
        int r = row0 + ty + i * 16;
        #pragma unroll
        for (int j = 0; j < 4; j++) {
            int c = col0 + tx + j * 16;
            float v = acc[i][j] + bias[c];
            if (GELU) v = 0.5f * v * (1.0f + erff(v * 0.70710678118654752f));
            if (RES)  v += res[r * N + c];
            C[r * N + c] = v;
        }
    }
}

// ---------------- attention part 1: partial M = K_h^T V_h over an S-chunk ----------------
__global__ void __launch_bounds__(256) attn_m_k() {
    const int h = blockIdx.x, chunk = blockIdx.y;
    __shared__ float Ks[32][65];
    __shared__ float Vs[32][65];
    const int tid = threadIdx.x;
    const int tx = tid & 15, ty = tid >> 4;
    float acc[4][4] = {};
    const int sbase = chunk * (SQ / NCHUNK);
    for (int s0 = 0; s0 < SQ / NCHUNK; s0 += 32) {
        #pragma unroll
        for (int i = 0; i < 8; i++) {
            int idx = tid + i * 256;
            int r = idx >> 6, c = idx & 63;
            int gidx = (sbase + s0 + r) * EM + h * 64 + c;
            Ks[r][c] = g_k[gidx];
            Vs[r][c] = g_v[gidx];
        }
        __syncthreads();
        #pragma unroll
        for (int ss = 0; ss < 32; ss++) {
            float a[4], bb[4];
            #pragma unroll
            for (int i = 0; i < 4; i++) a[i]  = Ks[ss][ty + i * 16];
            #pragma unroll
            for (int j = 0; j < 4; j++) bb[j] = Vs[ss][tx + j * 16];
            #pragma unroll
            for (int i = 0; i < 4; i++)
                #pragma unroll
                for (int j = 0; j < 4; j++)
                    acc[i][j] += a[i] * bb[j];
        }
        __syncthreads();
    }
    #pragma unroll
    for (int i = 0; i < 4; i++)
        #pragma unroll
        for (int j = 0; j < 4; j++)
            g_Mp[((h * NCHUNK + chunk) * 64 + ty + i * 16) * 64 + tx + j * 16] = acc[i][j];
}

// ---------------- attention part 2: O_h = scale * Q_h @ M_h ----------------
__global__ void __launch_bounds__(256) attn_o_k() {
    const int h = blockIdx.x, sb = blockIdx.y;
    __shared__ float Ms[64][65];
    __shared__ float Qs[64][65];
    const int tid = threadIdx.x;
    const int tx = tid & 15, ty = tid >> 4;
    // sum the NCHUNK partials of M_h into smem
    #pragma unroll
    for (int i = 0; i < 16; i++) {
        int idx = tid + i * 256;   // 4096 elems
        int d1 = idx >> 6, d2 = idx & 63;
        float s = 0.f;
        #pragma unroll
        for (int c = 0; c < NCHUNK; c++)
            s += g_Mp[((h * NCHUNK + c) * 64 + d1) * 64 + d2];
        Ms[d1][d2] = s;
    }
    const int row0 = sb * 64;
    #pragma unroll
    for (int i = 0; i < 16; i++) {
        int idx = tid + i * 256;
        int r = idx >> 6, c = idx & 63;
        Qs[r][c] = g_q[(row0 + r) * EM + h * 64 + c];
    }
    __syncthreads();
    float acc[4][4] = {};
    #pragma unroll
    for (int d = 0; d < 64; d++) {
        float a[4], bb[4];
        #pragma unroll
        for (int i = 0; i < 4; i++) a[i]  = Qs[ty + i * 16][d];
        #pragma unroll
        for (int j = 0; j < 4; j++) bb[j] = Ms[d][tx + j * 16];
        #pragma unroll
        for (int i = 0; i < 4; i++)
            #pragma unroll
            for (int j = 0; j < 4; j++)
                acc[i][j] += a[i] * bb[j];
    }
    const float scale = 0.125f; // DH^-0.5 = 1/8
    #pragma unroll
    for (int i = 0; i < 4; i++)
        #pragma unroll
        for (int j = 0; j < 4; j++)
            g_ao[(row0 + ty + i * 16) * EM + h * 64 + tx + j * 16] = acc[i][j] * scale;
}

// ---------------- host ----------------
extern "C" void kernel_launch(void* const* d_in, const int* in_sizes, int n_in,
                              void* d_out, int out_size) {
    const float* emb   = (const float*)d_in[0];
    const float* wpe   = (const float*)d_in[1];
    const float* ln1_g = (const float*)d_in[2];
    const float* ln1_b = (const float*)d_in[3];
    const float* Wq    = (const float*)d_in[4];
    const float* bq    = (const float*)d_in[5];
    const float* Wk    = (const float*)d_in[6];
    const float* bk    = (const float*)d_in[7];
    const float* Wv    = (const float*)d_in[8];
    const float* bv    = (const float*)d_in[9];
    const float* Wo    = (const float*)d_in[10];
    const float* bo    = (const float*)d_in[11];
    const float* ln2_g = (const float*)d_in[12];
    const float* ln2_b = (const float*)d_in[13];
    const float* W1    = (const float*)d_in[14];
    const float* b1    = (const float*)d_in[15];
    const float* W2    = (const float*)d_in[16];
    const float* b2    = (const float*)d_in[17];
    const float* lnf_g = (const float*)d_in[18];
    const float* lnf_b = (const float*)d_in[19];
    float* out = (float*)d_out;

    float *px, *ph, *pq, *pk, *pv, *pao, *pff;
    cudaGetSymbolAddress((void**)&px,  g_x);
    cudaGetSymbolAddress((void**)&ph,  g_h);
    cudaGetSymbolAddress((void**)&pq,  g_q);
    cudaGetSymbolAddress((void**)&pk,  g_k);
    cudaGetSymbolAddress((void**)&pv,  g_v);
    cudaGetSymbolAddress((void**)&pao, g_ao);
    cudaGetSymbolAddress((void**)&pff, g_ff);

    add_wpe_k<<<(SQ*EM + 255) / 256, 256>>>(emb, wpe);

    const dim3 gE(EM / 64, SQ / 64);     // GEMMs into [S, E]
    const dim3 gF(FFD / 64, SQ / 64);    // GEMM into [S, FF]

    for (int l = 0; l < NL; l++) {
        const float* Wq_l = Wq + (size_t)l * EM * EM;
        const float* Wk_l = Wk + (size_t)l * EM * EM;
        const float* Wv_l = Wv + (size_t)l * EM * EM;
        const float* Wo_l = Wo + (size_t)l * EM * EM;
        const float* W1_l = W1 + (size_t)l * EM * FFD;
        const float* W2_l = W2 + (size_t)l * FFD * EM;

        layernorm_k<<<SQ, 256>>>(px, ph, ln1_g + l * EM, ln1_b + l * EM);
        gemm64_k<false, false><<<gE, 256>>>(ph, Wq_l, bq + l * EM, nullptr, pq, SQ, EM, EM);
        gemm64_k<false, false><<<gE, 256>>>(ph, Wk_l, bk + l * EM, nullptr, pk, SQ, EM, EM);
        gemm64_k<false, false><<<gE, 256>>>(ph, Wv_l, bv + l * EM, nullptr, pv, SQ, EM, EM);
        attn_m_k<<<dim3(NH, NCHUNK), 256>>>();
        attn_o_k<<<dim3(NH, SQ / 64), 256>>>();
        gemm64_k<false, true ><<<gE, 256>>>(pao, Wo_l, bo + l * EM, px, px, SQ, EM, EM);
        layernorm_k<<<SQ, 256>>>(px, ph, ln2_g + l * EM, ln2_b + l * EM);
        gemm64_k<true,  false><<<gF, 256>>>(ph, W1_l, b1 + l * FFD, nullptr, pff, SQ, FFD, EM);
        gemm64_k<false, true ><<<gE, 256>>>(pff, W2_l, b2 + l * EM, px, px, SQ, EM, FFD);
    }

    layernorm_k<<<SQ, 256>>>(px, out, lnf_g, lnf_b);
}

// round 3
// speedup vs baseline: 3.1107x; 3.1107x over previous
#include <cuda_runtime.h>
#include <math.h>
#include <stdint.h>

#define SQ   2048
#define EM   768
#define NH   12
#define DH   64
#define FFD  3072
#define NL   4
#define EPSF 1e-5f
#define NCHUNK 8

// GEMM tiling
#define BM 128
#define BN 128
#define BK 32
#define AST 36      // A smem row stride (floats): banks (4g+q)%32 distinct
#define BST 136     // B smem row stride (floats): banks (8q+g)%32 distinct
#define A_STAGE (BM*AST)
#define B_STAGE (BK*BST)
#define SMEM_FLOATS (2*(A_STAGE+B_STAGE))
#define SMEM_BYTES  (SMEM_FLOATS*4)

// ---------------- scratch (no allocations allowed) ----------------
__device__ float g_x[SQ*EM];     // residual stream
__device__ float g_h[SQ*EM];     // layernorm output
__device__ float g_q[SQ*EM];
__device__ float g_k[SQ*EM];
__device__ float g_v[SQ*EM];
__device__ float g_ao[SQ*EM];    // attention output (pre o-proj)
__device__ float g_ff[SQ*FFD];   // MLP hidden
__device__ float g_Mp[NH*NCHUNK*DH*DH]; // partial K^T V per head per chunk

// ---------------- helpers ----------------
__device__ __forceinline__ uint32_t f2tf(float f) {
    uint32_t u;
    asm("cvt.rna.tf32.f32 %0, %1;" : "=r"(u) : "f"(f));
    return u;
}

// hi/lo split for 3xTF32: f ~= hi + lo with hi,lo representable in tf32
__device__ __forceinline__ void split_tf32(float f, uint32_t& hi, uint32_t& lo) {
    hi = f2tf(f);
    lo = f2tf(f - __uint_as_float(hi));
}

__device__ __forceinline__ void mma8(float c[4], const uint32_t a[4], const uint32_t b[2]) {
    asm volatile(
        "mma.sync.aligned.m16n8k8.row.col.f32.tf32.tf32.f32 "
        "{%0,%1,%2,%3},{%4,%5,%6,%7},{%8,%9},{%0,%1,%2,%3};\n"
        : "+f"(c[0]), "+f"(c[1]), "+f"(c[2]), "+f"(c[3])
        : "r"(a[0]), "r"(a[1]), "r"(a[2]), "r"(a[3]), "r"(b[0]), "r"(b[1]));
}

__device__ __forceinline__ void cpa16(uint32_t dst, const void* src) {
    asm volatile("cp.async.cg.shared.global [%0], [%1], 16;\n" :: "r"(dst), "l"(src) : "memory");
}
__device__ __forceinline__ void cp_commit() {
    asm volatile("cp.async.commit_group;\n" ::: "memory");
}
__device__ __forceinline__ void cp_wait1() {
    asm volatile("cp.async.wait_group 1;\n" ::: "memory");
}
__device__ __forceinline__ void cp_wait0() {
    asm volatile("cp.async.wait_group 0;\n" ::: "memory");
}

// ---------------- x = emb + wpe ----------------
__global__ void add_wpe_k(const float* __restrict__ emb, const float* __restrict__ wpe) {
    int i = blockIdx.x * blockDim.x + threadIdx.x;
    if (i < SQ*EM) g_x[i] = emb[i] + wpe[i];
}

// ---------------- layernorm: one block per row ----------------
__global__ void layernorm_k(const float* __restrict__ in, float* __restrict__ out,
                            const float* __restrict__ g, const float* __restrict__ b) {
    int row = blockIdx.x;
    const float* x = in + row * EM;
    float s = 0.f, s2 = 0.f;
    for (int j = threadIdx.x; j < EM; j += 256) {
        float v = x[j];
        s += v; s2 += v * v;
    }
    __shared__ float rs[32], rs2[32];
    #pragma unroll
    for (int o = 16; o; o >>= 1) {
        s  += __shfl_down_sync(0xffffffffu, s,  o);
        s2 += __shfl_down_sync(0xffffffffu, s2, o);
    }
    int w = threadIdx.x >> 5, l = threadIdx.x & 31;
    if (l == 0) { rs[w] = s; rs2[w] = s2; }
    __syncthreads();
    if (w == 0) {
        s  = (l < 8) ? rs[l]  : 0.f;
        s2 = (l < 8) ? rs2[l] : 0.f;
        #pragma unroll
        for (int o = 4; o; o >>= 1) {
            s  += __shfl_down_sync(0xffffffffu, s,  o);
            s2 += __shfl_down_sync(0xffffffffu, s2, o);
        }
        if (l == 0) { rs[0] = s; rs2[0] = s2; }
    }
    __syncthreads();
    float mu  = rs[0] * (1.0f / EM);
    float var = rs2[0] * (1.0f / EM) - mu * mu;
    float inv = rsqrtf(var + EPSF);
    for (int j = threadIdx.x; j < EM; j += 256)
        out[row * EM + j] = (x[j] - mu) * inv * g[j] + b[j];
}

// ---------------- 3xTF32 tensor-core GEMM body ----------------
// C[row0:+128, col0:+128] = epi(A[M,K] @ W[K,N] + bias [, +res])
template<bool GELU, bool RES>
__device__ __forceinline__ void gemm_body(
    const float* __restrict__ A, const float* __restrict__ W,
    const float* __restrict__ bias, const float* __restrict__ res,
    float* __restrict__ C, int N, int K, int row0, int col0, float* smem)
{
    float* As = smem;
    float* Bs = smem + 2 * A_STAGE;
    const int tid  = threadIdx.x;
    const int lane = tid & 31, warp = tid >> 5;
    const int wm = warp >> 2, wn = warp & 3;   // 2 x 4 warp grid
    const int g = lane >> 2, q = lane & 3;

    uint32_t sA = (uint32_t)__cvta_generic_to_shared(As);
    uint32_t sB = (uint32_t)__cvta_generic_to_shared(Bs);

    float acc[4][4][4];
    #pragma unroll
    for (int i = 0; i < 4; i++)
        #pragma unroll
        for (int j = 0; j < 4; j++)
            #pragma unroll
            for (int t = 0; t < 4; t++) acc[i][j][t] = 0.f;

    const int KT = K / BK;

    // tile loader: A 128x32 + B 32x128, 4+4 float4 per thread
    auto load_tile = [&](int kt, int st) {
        const float* a0 = A + (size_t)row0 * K + kt * BK;
        #pragma unroll
        for (int t = 0; t < 4; t++) {
            int idx = tid + t * 256;
            int r = idx >> 3, c4 = idx & 7;
            cpa16(sA + (uint32_t)(st * A_STAGE + r * AST + c4 * 4) * 4,
                  a0 + (size_t)r * K + c4 * 4);
        }
        const float* b0 = W + (size_t)kt * BK * N + col0;
        #pragma unroll
        for (int t = 0; t < 4; t++) {
            int idx = tid + t * 256;
            int r = idx >> 5, c4 = idx & 31;
            cpa16(sB + (uint32_t)(st * B_STAGE + r * BST + c4 * 4) * 4,
                  b0 + (size_t)r * N + c4 * 4);
        }
        cp_commit();
    };

    load_tile(0, 0);
    for (int kt = 0; kt < KT; kt++) {
        if (kt + 1 < KT) { load_tile(kt + 1, (kt + 1) & 1); cp_wait1(); }
        else             { cp_wait0(); }
        __syncthreads();

        const float* Ast = As + (kt & 1) * A_STAGE;
        const float* Bst = Bs + (kt & 1) * B_STAGE;

        #pragma unroll
        for (int ks = 0; ks < 4; ks++) {
            uint32_t ah[4][4], al[4][4], bh[4][2], bl[4][2];
            #pragma unroll
            for (int mi = 0; mi < 4; mi++) {
                int r = wm * 64 + mi * 16 + g;
                const float* p = Ast + r * AST + ks * 8 + q;
                split_tf32(p[0],            ah[mi][0], al[mi][0]);
                split_tf32(p[8 * AST],      ah[mi][1], al[mi][1]);
                split_tf32(p[4],            ah[mi][2], al[mi][2]);
                split_tf32(p[8 * AST + 4],  ah[mi][3], al[mi][3]);
            }
            #pragma unroll
            for (int ni = 0; ni < 4; ni++) {
                int cc = wn * 32 + ni * 8 + g;
                const float* p = Bst + (ks * 8 + q) * BST + cc;
                split_tf32(p[0],       bh[ni][0], bl[ni][0]);
                split_tf32(p[4 * BST], bh[ni][1], bl[ni][1]);
            }
            // 3xTF32: hi*hi + lo*hi + hi*lo (lo*lo negligible)
            #pragma unroll
            for (int mi = 0; mi < 4; mi++)
                #pragma unroll
                for (int ni = 0; ni < 4; ni++) {
                    mma8(acc[mi][ni], al[mi], bh[ni]);
                    mma8(acc[mi][ni], ah[mi], bl[ni]);
                    mma8(acc[mi][ni], ah[mi], bh[ni]);
                }
        }
        __syncthreads();
    }

    // epilogue
    #pragma unroll
    for (int mi = 0; mi < 4; mi++) {
        #pragma unroll
        for (int ni = 0; ni < 4; ni++) {
            int r0 = row0 + wm * 64 + mi * 16 + g;
            int c0 = col0 + wn * 32 + ni * 8 + 2 * q;
            float bb0 = bias[c0], bb1 = bias[c0 + 1];
            #pragma unroll
            for (int h = 0; h < 2; h++) {
                int r = r0 + h * 8;
                float v0 = acc[mi][ni][2 * h]     + bb0;
                float v1 = acc[mi][ni][2 * h + 1] + bb1;
                if (GELU) {
                    v0 = 0.5f * v0 * (1.0f + erff(v0 * 0.70710678118654752f));
                    v1 = 0.5f * v1 * (1.0f + erff(v1 * 0.70710678118654752f));
                }
                if (RES) {
                    v0 += res[(size_t)r * N + c0];
                    v1 += res[(size_t)r * N + c0 + 1];
                }
                C[(size_t)r * N + c0]     = v0;
                C[(size_t)r * N + c0 + 1] = v1;
            }
        }
    }
}

template<bool GELU, bool RES>
__global__ void __launch_bounds__(256, 2)
gemm_tc(const float* __restrict__ A, const float* __restrict__ W,
        const float* __restrict__ bias, const float* __restrict__ res,
        float* __restrict__ C, int N, int K) {
    extern __shared__ float smem[];
    gemm_body<GELU, RES>(A, W, bias, res, C, N, K,
                         blockIdx.y * BM, blockIdx.x * BN, smem);
}

// fused QKV: grid.x = 3 * (EM/BN); selects matrix per block
__global__ void __launch_bounds__(256, 2)
qkv_tc(const float* __restrict__ A,
       const float* __restrict__ Wq, const float* __restrict__ Wk, const float* __restrict__ Wv,
       const float* __restrict__ bq, const float* __restrict__ bk, const float* __restrict__ bv,
       float* __restrict__ Q, float* __restrict__ Ko, float* __restrict__ V, int K) {
    extern __shared__ float smem[];
    const int nb = EM / BN;   // 6
    int m = blockIdx.x / nb, cb = blockIdx.x % nb;
    const float* W = (m == 0) ? Wq : (m == 1) ? Wk : Wv;
    const float* b = (m == 0) ? bq : (m == 1) ? bk : bv;
    float*       C = (m == 0) ? Q  : (m == 1) ? Ko : V;
    gemm_body<false, false>(A, W, b, nullptr, C, EM, K,
                            blockIdx.y * BM, cb * BN, smem);
}

// ---------------- attention part 1: partial M = K_h^T V_h over an S-chunk ----------------
__global__ void __launch_bounds__(256) attn_m_k() {
    const int h = blockIdx.x, chunk = blockIdx.y;
    __shared__ float Ks[32][65];
    __shared__ float Vs[32][65];
    const int tid = threadIdx.x;
    const int tx = tid & 15, ty = tid >> 4;
    float acc[4][4] = {};
    const int sbase = chunk * (SQ / NCHUNK);
    for (int s0 = 0; s0 < SQ / NCHUNK; s0 += 32) {
        #pragma unroll
        for (int i = 0; i < 8; i++) {
            int idx = tid + i * 256;
            int r = idx >> 6, c = idx & 63;
            int gidx = (sbase + s0 + r) * EM + h * 64 + c;
            Ks[r][c] = g_k[gidx];
            Vs[r][c] = g_v[gidx];
        }
        __syncthreads();
        #pragma unroll
        for (int ss = 0; ss < 32; ss++) {
            float a[4], bb[4];
            #pragma unroll
            for (int i = 0; i < 4; i++) a[i]  = Ks[ss][ty + i * 16];
            #pragma unroll
            for (int j = 0; j < 4; j++) bb[j] = Vs[ss][tx + j * 16];
            #pragma unroll
            for (int i = 0; i < 4; i++)
                #pragma unroll
                for (int j = 0; j < 4; j++)
                    acc[i][j] += a[i] * bb[j];
        }
        __syncthreads();
    }
    #pragma unroll
    for (int i = 0; i < 4; i++)
        #pragma unroll
        for (int j = 0; j < 4; j++)
            g_Mp[((h * NCHUNK + chunk) * 64 + ty + i * 16) * 64 + tx + j * 16] = acc[i][j];
}

// ---------------- attention part 2: O_h = scale * Q_h @ M_h ----------------
__global__ void __launch_bounds__(256) attn_o_k() {
    const int h = blockIdx.x, sb = blockIdx.y;
    __shared__ float Ms[64][65];
    __shared__ float Qs[64][65];
    const int tid = threadIdx.x;
    const int tx = tid & 15, ty = tid >> 4;
    #pragma unroll
    for (int i = 0; i < 16; i++) {
        int idx = tid + i * 256;
        int d1 = idx >> 6, d2 = idx & 63;
        float s = 0.f;
        #pragma unroll
        for (int c = 0; c < NCHUNK; c++)
            s += g_Mp[((h * NCHUNK + c) * 64 + d1) * 64 + d2];
        Ms[d1][d2] = s;
    }
    const int row0 = sb * 64;
    #pragma unroll
    for (int i = 0; i < 16; i++) {
        int idx = tid + i * 256;
        int r = idx >> 6, c = idx & 63;
        Qs[r][c] = g_q[(row0 + r) * EM + h * 64 + c];
    }
    __syncthreads();
    float acc[4][4] = {};
    #pragma unroll
    for (int d = 0; d < 64; d++) {
        float a[4], bb[4];
        #pragma unroll
        for (int i = 0; i < 4; i++) a[i]  = Qs[ty + i * 16][d];
        #pragma unroll
        for (int j = 0; j < 4; j++) bb[j] = Ms[d][tx + j * 16];
        #pragma unroll
        for (int i = 0; i < 4; i++)
            #pragma unroll
            for (int j = 0; j < 4; j++)
                acc[i][j] += a[i] * bb[j];
    }
    const float scale = 0.125f;
    #pragma unroll
    for (int i = 0; i < 4; i++)
        #pragma unroll
        for (int j = 0; j < 4; j++)
            g_ao[(row0 + ty + i * 16) * EM + h * 64 + tx + j * 16] = acc[i][j] * scale;
}

// ---------------- host ----------------
extern "C" void kernel_launch(void* const* d_in, const int* in_sizes, int n_in,
                              void* d_out, int out_size) {
    const float* emb   = (const float*)d_in[0];
    const float* wpe   = (const float*)d_in[1];
    const float* ln1_g = (const float*)d_in[2];
    const float* ln1_b = (const float*)d_in[3];
    const float* Wq    = (const float*)d_in[4];
    const float* bq    = (const float*)d_in[5];
    const float* Wk    = (const float*)d_in[6];
    const float* bk    = (const float*)d_in[7];
    const float* Wv    = (const float*)d_in[8];
    const float* bv    = (const float*)d_in[9];
    const float* Wo    = (const float*)d_in[10];
    const float* bo    = (const float*)d_in[11];
    const float* ln2_g = (const float*)d_in[12];
    const float* ln2_b = (const float*)d_in[13];
    const float* W1    = (const float*)d_in[14];
    const float* b1    = (const float*)d_in[15];
    const float* W2    = (const float*)d_in[16];
    const float* b2    = (const float*)d_in[17];
    const float* lnf_g = (const float*)d_in[18];
    const float* lnf_b = (const float*)d_in[19];
    float* out = (float*)d_out;

    float *px, *ph, *pq, *pk, *pv, *pao, *pff;
    cudaGetSymbolAddress((void**)&px,  g_x);
    cudaGetSymbolAddress((void**)&ph,  g_h);
    cudaGetSymbolAddress((void**)&pq,  g_q);
    cudaGetSymbolAddress((void**)&pk,  g_k);
    cudaGetSymbolAddress((void**)&pv,  g_v);
    cudaGetSymbolAddress((void**)&pao, g_ao);
    cudaGetSymbolAddress((void**)&pff, g_ff);

    cudaFuncSetAttribute(gemm_tc<false, true>,
                         cudaFuncAttributeMaxDynamicSharedMemorySize, SMEM_BYTES);
    cudaFuncSetAttribute(gemm_tc<true, false>,
                         cudaFuncAttributeMaxDynamicSharedMemorySize, SMEM_BYTES);
    cudaFuncSetAttribute(qkv_tc,
                         cudaFuncAttributeMaxDynamicSharedMemorySize, SMEM_BYTES);

    add_wpe_k<<<(SQ*EM + 255) / 256, 256>>>(emb, wpe);

    const dim3 gQKV(3 * (EM / BN), SQ / BM);   // (18, 16)
    const dim3 gE(EM / BN,  SQ / BM);          // (6, 16)
    const dim3 gF(FFD / BN, SQ / BM);          // (24, 16)

    for (int l = 0; l < NL; l++) {
        const float* Wq_l = Wq + (size_t)l * EM * EM;
        const float* Wk_l = Wk + (size_t)l * EM * EM;
        const float* Wv_l = Wv + (size_t)l * EM * EM;
        const float* Wo_l = Wo + (size_t)l * EM * EM;
        const float* W1_l = W1 + (size_t)l * EM * FFD;
        const float* W2_l = W2 + (size_t)l * FFD * EM;

        layernorm_k<<<SQ, 256>>>(px, ph, ln1_g + l * EM, ln1_b + l * EM);
        qkv_tc<<<gQKV, 256, SMEM_BYTES>>>(ph, Wq_l, Wk_l, Wv_l,
                                          bq + l * EM, bk + l * EM, bv + l * EM,
                                          pq, pk, pv, EM);
        attn_m_k<<<dim3(NH, NCHUNK), 256>>>();
        attn_o_k<<<dim3(NH, SQ / 64), 256>>>();
        gemm_tc<false, true ><<<gE, 256, SMEM_BYTES>>>(pao, Wo_l, bo + l * EM, px, px, EM, EM);
        layernorm_k<<<SQ, 256>>>(px, ph, ln2_g + l * EM, ln2_b + l * EM);
        gemm_tc<true,  false><<<gF, 256, SMEM_BYTES>>>(ph,  W1_l, b1 + l * FFD, nullptr, pff, FFD, EM);
        gemm_tc<false, true ><<<gE, 256, SMEM_BYTES>>>(pff, W2_l, b2 + l * EM, px, px, EM, FFD);
    }

    layernorm_k<<<SQ, 256>>>(px, out, lnf_g, lnf_b);
}

// round 4
// speedup vs baseline: 4.5690x; 1.4688x over previous
#include <cuda_runtime.h>
#include <cuda_bf16.h>
#include <math.h>
#include <stdint.h>

#define SQ   2048
#define EM   768
#define NH   12
#define DH   64
#define FFD  3072
#define NL   4
#define EPSF 1e-5f
#define NCHUNK 8

// GEMM tiling: BM=BN=128, BK=32, 256 threads, warp tile 64x32, bf16 m16n8k16 x3 terms
#define BM 128
#define BN 128
#define BK 32
#define RSTR 20            // smem row stride in u32 (16 used + 4 pad): banks 20g+q all distinct
#define AH_OFF 0
#define AL_OFF 2560
#define BH_OFF 5120
#define BL_OFF 7680
#define STAGE_U32 10240
#define SMEM_BYTES (2*STAGE_U32*4)   // 81920

// weight region offsets in the transposed/split weight pool (elements)
#define WMAT   589824            // 768*768
#define W1MAT  2359296           // 768*3072
#define OFF_WQ 0
#define OFF_WK (4*WMAT)
#define OFF_WV (8*WMAT)
#define OFF_WO (12*WMAT)
#define OFF_W1 (16*WMAT)
#define OFF_W2 (16*WMAT + 4*W1MAT)
#define WTOTAL (16*WMAT + 8*W1MAT)  // 28311552

// ---------------- scratch (no allocations allowed) ----------------
__device__ float g_x[SQ*EM];                 // residual stream (fp32)
__device__ float g_q[SQ*EM];
__device__ float g_k[SQ*EM];
__device__ float g_v[SQ*EM];
__device__ float g_Mp[NH*NCHUNK*DH*DH];      // partial K^T V
__device__ __nv_bfloat16 gwt_hi[WTOTAL];     // transposed weights, hi part
__device__ __nv_bfloat16 gwt_lo[WTOTAL];     // transposed weights, lo part
__device__ __nv_bfloat16 gh_hi[SQ*EM],  gh_lo[SQ*EM];    // LN output split
__device__ __nv_bfloat16 gao_hi[SQ*EM], gao_lo[SQ*EM];   // attn output split
__device__ __nv_bfloat16 gff_hi[SQ*FFD], gff_lo[SQ*FFD]; // MLP hidden split

// ---------------- helpers ----------------
__device__ __forceinline__ void mma_bf16(float c[4], const uint32_t a[4], const uint32_t b[2]) {
    asm volatile(
        "mma.sync.aligned.m16n8k16.row.col.f32.bf16.bf16.f32 "
        "{%0,%1,%2,%3},{%4,%5,%6,%7},{%8,%9},{%0,%1,%2,%3};\n"
        : "+f"(c[0]), "+f"(c[1]), "+f"(c[2]), "+f"(c[3])
        : "r"(a[0]), "r"(a[1]), "r"(a[2]), "r"(a[3]), "r"(b[0]), "r"(b[1]));
}
__device__ __forceinline__ void cpa16(uint32_t dst, const void* src) {
    asm volatile("cp.async.cg.shared.global [%0], [%1], 16;\n" :: "r"(dst), "l"(src) : "memory");
}
__device__ __forceinline__ void cp_commit() { asm volatile("cp.async.commit_group;\n" ::: "memory"); }
__device__ __forceinline__ void cp_wait1()  { asm volatile("cp.async.wait_group 1;\n" ::: "memory"); }
__device__ __forceinline__ void cp_wait0()  { asm volatile("cp.async.wait_group 0;\n" ::: "memory"); }

__device__ __forceinline__ void split_bf(float v, __nv_bfloat16& hi, __nv_bfloat16& lo) {
    hi = __float2bfloat16_rn(v);
    lo = __float2bfloat16_rn(v - __bfloat162float(hi));
}

// ---------------- weight transpose + split: src[L][K][N] -> dst[L][N][K] (hi,lo bf16) ----------------
__global__ void wconv_k(const float* __restrict__ src,
                        __nv_bfloat16* __restrict__ dhi, __nv_bfloat16* __restrict__ dlo,
                        int K, int N) {
    __shared__ float t[32][33];
    const size_t lofs = (size_t)blockIdx.z * K * N;
    const int n0 = blockIdx.x * 32, k0 = blockIdx.y * 32;
    const int tx = threadIdx.x, ty = threadIdx.y;
    #pragma unroll
    for (int i = 0; i < 4; i++)
        t[ty + 8*i][tx] = src[lofs + (size_t)(k0 + ty + 8*i) * N + n0 + tx];
    __syncthreads();
    #pragma unroll
    for (int i = 0; i < 4; i++) {
        float v = t[tx][ty + 8*i];
        size_t o = lofs + (size_t)(n0 + ty + 8*i) * K + k0 + tx;
        __nv_bfloat16 h, l;
        split_bf(v, h, l);
        dhi[o] = h; dlo[o] = l;
    }
}

// ---------------- x = emb + wpe ----------------
__global__ void add_wpe_k(const float* __restrict__ emb, const float* __restrict__ wpe) {
    int i = blockIdx.x * blockDim.x + threadIdx.x;
    if (i < SQ*EM) g_x[i] = emb[i] + wpe[i];
}

// ---------------- layernorm: one block per row; SPLIT -> bf16 hi/lo, else fp32 ----------------
template<bool SPLIT>
__global__ void layernorm_k(const float* __restrict__ in, float* __restrict__ outf,
                            __nv_bfloat16* __restrict__ ohi, __nv_bfloat16* __restrict__ olo,
                            const float* __restrict__ g, const float* __restrict__ b) {
    int row = blockIdx.x;
    const float* x = in + row * EM;
    float s = 0.f, s2 = 0.f;
    for (int j = threadIdx.x; j < EM; j += 256) {
        float v = x[j];
        s += v; s2 += v * v;
    }
    __shared__ float rs[32], rs2[32];
    #pragma unroll
    for (int o = 16; o; o >>= 1) {
        s  += __shfl_down_sync(0xffffffffu, s,  o);
        s2 += __shfl_down_sync(0xffffffffu, s2, o);
    }
    int w = threadIdx.x >> 5, l = threadIdx.x & 31;
    if (l == 0) { rs[w] = s; rs2[w] = s2; }
    __syncthreads();
    if (w == 0) {
        s  = (l < 8) ? rs[l]  : 0.f;
        s2 = (l < 8) ? rs2[l] : 0.f;
        #pragma unroll
        for (int o = 4; o; o >>= 1) {
            s  += __shfl_down_sync(0xffffffffu, s,  o);
            s2 += __shfl_down_sync(0xffffffffu, s2, o);
        }
        if (l == 0) { rs[0] = s; rs2[0] = s2; }
    }
    __syncthreads();
    float mu  = rs[0] * (1.0f / EM);
    float var = rs2[0] * (1.0f / EM) - mu * mu;
    float inv = rsqrtf(var + EPSF);
    for (int j = threadIdx.x; j < EM; j += 256) {
        float v = (x[j] - mu) * inv * g[j] + b[j];
        if (SPLIT) {
            __nv_bfloat16 h, lo;
            split_bf(v, h, lo);
            ohi[row * EM + j] = h;
            olo[row * EM + j] = lo;
        } else {
            outf[row * EM + j] = v;
        }
    }
}

// ---------------- 3xBF16 tensor-core GEMM body ----------------
// A (hi/lo bf16, [M,K] row-major), B (hi/lo bf16, [N,K] k-major = transposed weights)
template<bool GELU, bool RES, bool OSPLIT>
__device__ __forceinline__ void gemm_body(
    const __nv_bfloat16* __restrict__ Ahi, const __nv_bfloat16* __restrict__ Alo,
    const __nv_bfloat16* __restrict__ Bhi, const __nv_bfloat16* __restrict__ Blo,
    const float* __restrict__ bias, const float* __restrict__ res,
    float* __restrict__ C, __nv_bfloat16* __restrict__ Chi, __nv_bfloat16* __restrict__ Clo,
    int N, int K, int row0, int col0, uint32_t* smem)
{
    const int tid  = threadIdx.x;
    const int lane = tid & 31, warp = tid >> 5;
    const int wm = warp >> 2, wn = warp & 3;   // 2 x 4 warp grid
    const int g = lane >> 2, q = lane & 3;

    uint32_t sbase = (uint32_t)__cvta_generic_to_shared(smem);

    float acc[4][4][4];
    #pragma unroll
    for (int i = 0; i < 4; i++)
        #pragma unroll
        for (int j = 0; j < 4; j++)
            #pragma unroll
            for (int t = 0; t < 4; t++) acc[i][j][t] = 0.f;

    const int KT = K / BK;

    auto load_tile = [&](int kt, int st) {
        uint32_t base = sbase + st * STAGE_U32 * 4;
        #pragma unroll
        for (int t = 0; t < 2; t++) {
            int chunk = tid + t * 256;             // 0..511
            int r = chunk >> 2, c4 = (chunk & 3) * 4;
            size_t aoff = (size_t)(row0 + r) * K + kt * BK + (chunk & 3) * 8;
            cpa16(base + (uint32_t)(AH_OFF + r * RSTR + c4) * 4, Ahi + aoff);
            cpa16(base + (uint32_t)(AL_OFF + r * RSTR + c4) * 4, Alo + aoff);
            size_t boff = (size_t)(col0 + r) * K + kt * BK + (chunk & 3) * 8;
            cpa16(base + (uint32_t)(BH_OFF + r * RSTR + c4) * 4, Bhi + boff);
            cpa16(base + (uint32_t)(BL_OFF + r * RSTR + c4) * 4, Blo + boff);
        }
        cp_commit();
    };

    load_tile(0, 0);
    for (int kt = 0; kt < KT; kt++) {
        if (kt + 1 < KT) { load_tile(kt + 1, (kt + 1) & 1); cp_wait1(); }
        else             { cp_wait0(); }
        __syncthreads();

        const uint32_t* S = smem + (kt & 1) * STAGE_U32;

        #pragma unroll
        for (int ks = 0; ks < 2; ks++) {
            const int kq = ks * 8 + q;
            uint32_t ah[4][4], al[4][4], bh[4][2], bl[4][2];
            #pragma unroll
            for (int mi = 0; mi < 4; mi++) {
                int rb = (wm * 64 + mi * 16 + g) * RSTR + kq;
                ah[mi][0] = S[AH_OFF + rb];       ah[mi][1] = S[AH_OFF + rb + 8*RSTR];
                ah[mi][2] = S[AH_OFF + rb + 4];   ah[mi][3] = S[AH_OFF + rb + 8*RSTR + 4];
                al[mi][0] = S[AL_OFF + rb];       al[mi][1] = S[AL_OFF + rb + 8*RSTR];
                al[mi][2] = S[AL_OFF + rb + 4];   al[mi][3] = S[AL_OFF + rb + 8*RSTR + 4];
            }
            #pragma unroll
            for (int ni = 0; ni < 4; ni++) {
                int nb = (wn * 32 + ni * 8 + g) * RSTR + kq;
                bh[ni][0] = S[BH_OFF + nb];  bh[ni][1] = S[BH_OFF + nb + 4];
                bl[ni][0] = S[BL_OFF + nb];  bl[ni][1] = S[BL_OFF + nb + 4];
            }
            #pragma unroll
            for (int mi = 0; mi < 4; mi++)
                #pragma unroll
                for (int ni = 0; ni < 4; ni++) {
                    mma_bf16(acc[mi][ni], al[mi], bh[ni]);
                    mma_bf16(acc[mi][ni], ah[mi], bl[ni]);
                    mma_bf16(acc[mi][ni], ah[mi], bh[ni]);
                }
        }
        __syncthreads();
    }

    // epilogue (C layout: t0=(g,2q) t1=(g,2q+1) t2=(g+8,2q) t3=(g+8,2q+1))
    #pragma unroll
    for (int mi = 0; mi < 4; mi++) {
        #pragma unroll
        for (int ni = 0; ni < 4; ni++) {
            int r0 = row0 + wm * 64 + mi * 16 + g;
            int c0 = col0 + wn * 32 + ni * 8 + 2 * q;
            float bb0 = bias[c0], bb1 = bias[c0 + 1];
            #pragma unroll
            for (int h = 0; h < 2; h++) {
                int r = r0 + h * 8;
                float v0 = acc[mi][ni][2 * h]     + bb0;
                float v1 = acc[mi][ni][2 * h + 1] + bb1;
                if (GELU) {
                    v0 = 0.5f * v0 * (1.0f + erff(v0 * 0.70710678118654752f));
                    v1 = 0.5f * v1 * (1.0f + erff(v1 * 0.70710678118654752f));
                }
                if (RES) {
                    v0 += res[(size_t)r * N + c0];
                    v1 += res[(size_t)r * N + c0 + 1];
                }
                if (OSPLIT) {
                    __nv_bfloat16 h0, l0, h1, l1;
                    split_bf(v0, h0, l0);
                    split_bf(v1, h1, l1);
                    Chi[(size_t)r * N + c0]     = h0;  Clo[(size_t)r * N + c0]     = l0;
                    Chi[(size_t)r * N + c0 + 1] = h1;  Clo[(size_t)r * N + c0 + 1] = l1;
                } else {
                    C[(size_t)r * N + c0]     = v0;
                    C[(size_t)r * N + c0 + 1] = v1;
                }
            }
        }
    }
}

template<bool GELU, bool RES, bool OSPLIT>
__global__ void __launch_bounds__(256, 2)
gemm_tc(const __nv_bfloat16* __restrict__ Ahi, const __nv_bfloat16* __restrict__ Alo,
        const __nv_bfloat16* __restrict__ Bhi, const __nv_bfloat16* __restrict__ Blo,
        const float* __restrict__ bias, const float* __restrict__ res,
        float* __restrict__ C, __nv_bfloat16* __restrict__ Chi, __nv_bfloat16* __restrict__ Clo,
        int N, int K) {
    extern __shared__ uint32_t smem[];
    gemm_body<GELU, RES, OSPLIT>(Ahi, Alo, Bhi, Blo, bias, res, C, Chi, Clo,
                                 N, K, blockIdx.y * BM, blockIdx.x * BN, smem);
}

// fused QKV: grid.x = 3 * (EM/BN)
__global__ void __launch_bounds__(256, 2)
qkv_tc(const __nv_bfloat16* __restrict__ Bq_hi, const __nv_bfloat16* __restrict__ Bq_lo,
       const __nv_bfloat16* __restrict__ Bk_hi, const __nv_bfloat16* __restrict__ Bk_lo,
       const __nv_bfloat16* __restrict__ Bv_hi, const __nv_bfloat16* __restrict__ Bv_lo,
       const float* __restrict__ bq, const float* __restrict__ bk, const float* __restrict__ bv) {
    extern __shared__ uint32_t smem[];
    const int nb = EM / BN;   // 6
    int m = blockIdx.x / nb, cb = blockIdx.x % nb;
    const __nv_bfloat16* Bh = (m == 0) ? Bq_hi : (m == 1) ? Bk_hi : Bv_hi;
    const __nv_bfloat16* Bl = (m == 0) ? Bq_lo : (m == 1) ? Bk_lo : Bv_lo;
    const float* b = (m == 0) ? bq : (m == 1) ? bk : bv;
    float*       C = (m == 0) ? g_q : (m == 1) ? g_k : g_v;
    gemm_body<false, false, false>(gh_hi, gh_lo, Bh, Bl, b, nullptr, C, nullptr, nullptr,
                                   EM, EM, blockIdx.y * BM, cb * BN, smem);
}

// ---------------- attention part 1: partial M = K_h^T V_h over an S-chunk ----------------
__global__ void __launch_bounds__(256) attn_m_k() {
    const int h = blockIdx.x, chunk = blockIdx.y;
    __shared__ float Ks[32][65];
    __shared__ float Vs[32][65];
    const int tid = threadIdx.x;
    const int tx = tid & 15, ty = tid >> 4;
    float acc[4][4] = {};
    const int sbase = chunk * (SQ / NCHUNK);
    for (int s0 = 0; s0 < SQ / NCHUNK; s0 += 32) {
        #pragma unroll
        for (int i = 0; i < 8; i++) {
            int idx = tid + i * 256;
            int r = idx >> 6, c = idx & 63;
            int gidx = (sbase + s0 + r) * EM + h * 64 + c;
            Ks[r][c] = g_k[gidx];
            Vs[r][c] = g_v[gidx];
        }
        __syncthreads();
        #pragma unroll
        for (int ss = 0; ss < 32; ss++) {
            float a[4], bb[4];
            #pragma unroll
            for (int i = 0; i < 4; i++) a[i]  = Ks[ss][ty + i * 16];
            #pragma unroll
            for (int j = 0; j < 4; j++) bb[j] = Vs[ss][tx + j * 16];
            #pragma unroll
            for (int i = 0; i < 4; i++)
                #pragma unroll
                for (int j = 0; j < 4; j++)
                    acc[i][j] += a[i] * bb[j];
        }
        __syncthreads();
    }
    #pragma unroll
    for (int i = 0; i < 4; i++)
        #pragma unroll
        for (int j = 0; j < 4; j++)
            g_Mp[((h * NCHUNK + chunk) * 64 + ty + i * 16) * 64 + tx + j * 16] = acc[i][j];
}

// ---------------- attention part 2: O_h = scale * Q_h @ M_h  (writes hi/lo split) ----------------
__global__ void __launch_bounds__(256) attn_o_k() {
    const int h = blockIdx.x, sb = blockIdx.y;
    __shared__ float Ms[64][65];
    __shared__ float Qs[64][65];
    const int tid = threadIdx.x;
    const int tx = tid & 15, ty = tid >> 4;
    #pragma unroll
    for (int i = 0; i < 16; i++) {
        int idx = tid + i * 256;
        int d1 = idx >> 6, d2 = idx & 63;
        float s = 0.f;
        #pragma unroll
        for (int c = 0; c < NCHUNK; c++)
            s += g_Mp[((h * NCHUNK + c) * 64 + d1) * 64 + d2];
        Ms[d1][d2] = s;
    }
    const int row0 = sb * 64;
    #pragma unroll
    for (int i = 0; i < 16; i++) {
        int idx = tid + i * 256;
        int r = idx >> 6, c = idx & 63;
        Qs[r][c] = g_q[(row0 + r) * EM + h * 64 + c];
    }
    __syncthreads();
    float acc[4][4] = {};
    #pragma unroll
    for (int d = 0; d < 64; d++) {
        float a[4], bb[4];
        #pragma unroll
        for (int i = 0; i < 4; i++) a[i]  = Qs[ty + i * 16][d];
        #pragma unroll
        for (int j = 0; j < 4; j++) bb[j] = Ms[d][tx + j * 16];
        #pragma unroll
        for (int i = 0; i < 4; i++)
            #pragma unroll
            for (int j = 0; j < 4; j++)
                acc[i][j] += a[i] * bb[j];
    }
    const float scale = 0.125f;
    #pragma unroll
    for (int i = 0; i < 4; i++)
        #pragma unroll
        for (int j = 0; j < 4; j++) {
            float v = acc[i][j] * scale;
            __nv_bfloat16 h2, l2;
            split_bf(v, h2, l2);
            size_t o = (size_t)(row0 + ty + i * 16) * EM + h * 64 + tx + j * 16;
            gao_hi[o] = h2;
            gao_lo[o] = l2;
        }
}

// ---------------- host ----------------
extern "C" void kernel_launch(void* const* d_in, const int* in_sizes, int n_in,
                              void* d_out, int out_size) {
    const float* emb   = (const float*)d_in[0];
    const float* wpe   = (const float*)d_in[1];
    const float* ln1_g = (const float*)d_in[2];
    const float* ln1_b = (const float*)d_in[3];
    const float* Wq    = (const float*)d_in[4];
    const float* bq    = (const float*)d_in[5];
    const float* Wk    = (const float*)d_in[6];
    const float* bk    = (const float*)d_in[7];
    const float* Wv    = (const float*)d_in[8];
    const float* bv    = (const float*)d_in[9];
    const float* Wo    = (const float*)d_in[10];
    const float* bo    = (const float*)d_in[11];
    const float* ln2_g = (const float*)d_in[12];
    const float* ln2_b = (const float*)d_in[13];
    const float* W1    = (const float*)d_in[14];
    const float* b1    = (const float*)d_in[15];
    const float* W2    = (const float*)d_in[16];
    const float* b2    = (const float*)d_in[17];
    const float* lnf_g = (const float*)d_in[18];
    const float* lnf_b = (const float*)d_in[19];
    float* out = (float*)d_out;

    float *px;
    __nv_bfloat16 *pwh, *pwl, *phh, *phl, *pfh, *pfl, *paoh, *paol;
    cudaGetSymbolAddress((void**)&px,   g_x);
    cudaGetSymbolAddress((void**)&pwh,  gwt_hi);
    cudaGetSymbolAddress((void**)&pwl,  gwt_lo);
    cudaGetSymbolAddress((void**)&phh,  gh_hi);
    cudaGetSymbolAddress((void**)&phl,  gh_lo);
    cudaGetSymbolAddress((void**)&pfh,  gff_hi);
    cudaGetSymbolAddress((void**)&pfl,  gff_lo);
    cudaGetSymbolAddress((void**)&paoh, gao_hi);
    cudaGetSymbolAddress((void**)&paol, gao_lo);

    cudaFuncSetAttribute(gemm_tc<false, true, false>,
                         cudaFuncAttributeMaxDynamicSharedMemorySize, SMEM_BYTES);
    cudaFuncSetAttribute(gemm_tc<true, false, true>,
                         cudaFuncAttributeMaxDynamicSharedMemorySize, SMEM_BYTES);
    cudaFuncSetAttribute(qkv_tc,
                         cudaFuncAttributeMaxDynamicSharedMemorySize, SMEM_BYTES);

    // weight transpose + hi/lo split (all layers per matrix type)
    {
        dim3 blk(32, 8);
        wconv_k<<<dim3(EM/32,  EM/32,  NL), blk>>>(Wq, pwh + OFF_WQ, pwl + OFF_WQ, EM,  EM);
        wconv_k<<<dim3(EM/32,  EM/32,  NL), blk>>>(Wk, pwh + OFF_WK, pwl + OFF_WK, EM,  EM);
        wconv_k<<<dim3(EM/32,  EM/32,  NL), blk>>>(Wv, pwh + OFF_WV, pwl + OFF_WV, EM,  EM);
        wconv_k<<<dim3(EM/32,  EM/32,  NL), blk>>>(Wo, pwh + OFF_WO, pwl + OFF_WO, EM,  EM);
        wconv_k<<<dim3(FFD/32, EM/32,  NL), blk>>>(W1, pwh + OFF_W1, pwl + OFF_W1, EM,  FFD);
        wconv_k<<<dim3(EM/32,  FFD/32, NL), blk>>>(W2, pwh + OFF_W2, pwl + OFF_W2, FFD, EM);
    }

    add_wpe_k<<<(SQ*EM + 255) / 256, 256>>>(emb, wpe);

    const dim3 gQKV(3 * (EM / BN), SQ / BM);   // (18, 16)
    const dim3 gE(EM / BN,  SQ / BM);          // (6, 16)
    const dim3 gF(FFD / BN, SQ / BM);          // (24, 16)

    for (int l = 0; l < NL; l++) {
        const __nv_bfloat16* wq_h = pwh + OFF_WQ + (size_t)l * WMAT;
        const __nv_bfloat16* wq_l = pwl + OFF_WQ + (size_t)l * WMAT;
        const __nv_bfloat16* wk_h = pwh + OFF_WK + (size_t)l * WMAT;
        const __nv_bfloat16* wk_l = pwl + OFF_WK + (size_t)l * WMAT;
        const __nv_bfloat16* wv_h = pwh + OFF_WV + (size_t)l * WMAT;
        const __nv_bfloat16* wv_l = pwl + OFF_WV + (size_t)l * WMAT;
        const __nv_bfloat16* wo_h = pwh + OFF_WO + (size_t)l * WMAT;
        const __nv_bfloat16* wo_l = pwl + OFF_WO + (size_t)l * WMAT;
        const __nv_bfloat16* w1_h = pwh + OFF_W1 + (size_t)l * W1MAT;
        const __nv_bfloat16* w1_l = pwl + OFF_W1 + (size_t)l * W1MAT;
        const __nv_bfloat16* w2_h = pwh + OFF_W2 + (size_t)l * W1MAT;
        const __nv_bfloat16* w2_l = pwl + OFF_W2 + (size_t)l * W1MAT;

        layernorm_k<true><<<SQ, 256>>>(px, nullptr, phh, phl, ln1_g + l * EM, ln1_b + l * EM);
        qkv_tc<<<gQKV, 256, SMEM_BYTES>>>(wq_h, wq_l, wk_h, wk_l, wv_h, wv_l,
                                          bq + l * EM, bk + l * EM, bv + l * EM);
        attn_m_k<<<dim3(NH, NCHUNK), 256>>>();
        attn_o_k<<<dim3(NH, SQ / 64), 256>>>();
        gemm_tc<false, true, false><<<gE, 256, SMEM_BYTES>>>(
            paoh, paol, wo_h, wo_l, bo + l * EM, px, px, nullptr, nullptr, EM, EM);
        layernorm_k<true><<<SQ, 256>>>(px, nullptr, phh, phl, ln2_g + l * EM, ln2_b + l * EM);
        gemm_tc<true, false, true><<<gF, 256, SMEM_BYTES>>>(
            phh, phl, w1_h, w1_l, b1 + l * FFD, nullptr, nullptr, pfh, pfl, FFD, EM);
        gemm_tc<false, true, false><<<gE, 256, SMEM_BYTES>>>(
            pfh, pfl, w2_h, w2_l, b2 + l * EM, px, px, nullptr, nullptr, EM, FFD);
    }

    layernorm_k<false><<<SQ, 256>>>(px, out, nullptr, nullptr, lnf_g, lnf_b);
}